// round 12
// baseline (speedup 1.0000x reference)
#include <cuda_runtime.h>

// Problem constants
#define BATCH 8
#define NUM   128
#define CH    512          // = H * D_K
#define HEADS 8
#define DK    64
#define NPOS  (BATCH*NUM*NUM)   // 131072 positions (b, i, j)
#define NROWS (BATCH*NUM)       // 1024 (b, i) rows
#define EPSV  1e-8f

// Device globals (no allocs allowed).
__device__ float g_colmask[NUM];
__device__ int   g_counter;
__device__ int   g_flag;

// ---------------------------------------------------------------------------
// Kernel 1: cosine-similarity attention. FROZEN (78.5us @ 6.9TB/s ~ LTS cap).
// 256 threads/block, 4 positions/block; fully-coalesced float4 streaming
// loads (__ldcs), MLP=4, 16-lane xor reduction per position.
// Block 0 resets colmask/counter/flag (stream-ordered before kernel 2).
// ---------------------------------------------------------------------------
__global__ __launch_bounds__(256) void attn_kernel(
    const float* __restrict__ q,
    const float* __restrict__ k,
    float* __restrict__ out)
{
    const int tidx = threadIdx.x;           // 0..255
    const int t    = tidx & 127;            // float4 column within position
    const int posA = blockIdx.x * 4 + (tidx >> 7);
    const int posB = posA + 2;

    if (blockIdx.x == 0) {
        if (tidx < NUM) g_colmask[tidx] = 0.0f;
        if (tidx == 0) { g_counter = 0; g_flag = 0; }
    }

    const float4* qA = reinterpret_cast<const float4*>(q + (size_t)posA * CH);
    const float4* kA = reinterpret_cast<const float4*>(k + (size_t)posA * CH);
    const float4* qB = reinterpret_cast<const float4*>(q + (size_t)posB * CH);
    const float4* kB = reinterpret_cast<const float4*>(k + (size_t)posB * CH);

    // Front-batched, fully coalesced, streaming loads (MLP = 4).
    float4 a0 = __ldcs(qA + t);
    float4 b0 = __ldcs(kA + t);
    float4 a1 = __ldcs(qB + t);
    float4 b1 = __ldcs(kB + t);

    float dot0 = a0.x*b0.x + a0.y*b0.y + a0.z*b0.z + a0.w*b0.w;
    float qq0  = a0.x*a0.x + a0.y*a0.y + a0.z*a0.z + a0.w*a0.w;
    float kk0  = b0.x*b0.x + b0.y*b0.y + b0.z*b0.z + b0.w*b0.w;
    float dot1 = a1.x*b1.x + a1.y*b1.y + a1.z*b1.z + a1.w*b1.w;
    float qq1  = a1.x*a1.x + a1.y*a1.y + a1.z*a1.z + a1.w*a1.w;
    float kk1  = b1.x*b1.x + b1.y*b1.y + b1.z*b1.z + b1.w*b1.w;

    // Reduce across the 16 lanes of one head (both positions interleaved).
    #pragma unroll
    for (int m = 8; m; m >>= 1) {
        dot0 += __shfl_xor_sync(0xffffffffu, dot0, m);
        qq0  += __shfl_xor_sync(0xffffffffu, qq0,  m);
        kk0  += __shfl_xor_sync(0xffffffffu, kk0,  m);
        dot1 += __shfl_xor_sync(0xffffffffu, dot1, m);
        qq1  += __shfl_xor_sync(0xffffffffu, qq1,  m);
        kk1  += __shfl_xor_sync(0xffffffffu, kk1,  m);
    }

    if ((t & 15) == 0) {
        int h = t >> 4;
        float s0 = dot0 / fmaxf(sqrtf(qq0 * kk0), EPSV);
        float s1 = dot1 / fmaxf(sqrtf(qq1 * kk1), EPSV);
        out[(size_t)posA * HEADS + h] = fmaxf(s0, 0.0f);
        out[(size_t)posB * HEADS + h] = fmaxf(s1, 0.0f);
    }
}

// ---------------------------------------------------------------------------
// Kernel 2 (fused topk + apply), single wave: 1024 blocks, 256 threads,
// __launch_bounds__(256,8) -> <=32 regs -> 8 blocks/SM -> 1184 >= 1024.
//
// Phase A: per-(b,i,h) top-4 over j (warp per head), OR winners into
//          g_colmask. Tiebreak = lowest index (lax.top_k order).
// Barrier: 1 atomicAdd arrival per block; LAST arriver atomicExch's g_flag;
//          others poll g_flag with plain volatile LOADS (no atomic-RMW
//          serialization -- that was the R6 21us pathology).
// Phase B: out[row, j, :] *= roi[row, j] * colmask[j]; one float4/thread.
// ---------------------------------------------------------------------------
__global__ __launch_bounds__(256, 8) void topk_apply_kernel(
    float* __restrict__ out,
    const float* __restrict__ roi)
{
    __shared__ float sm[HEADS * 132];

    const int bi   = blockIdx.x;                  // (b*NUM + i)
    const int tidx = threadIdx.x;                 // 0..255
    float* row = out + (size_t)bi * NUM * HEADS;  // 128 j x 8 h

    // ---- Phase A: load + transpose into sm[h*132 + j] ----
    #pragma unroll
    for (int r = 0; r < 4; ++r) {
        int idx = tidx + r * 256;                 // idx = j*8 + h
        sm[(idx & 7) * 132 + (idx >> 3)] = row[idx];
    }
    __syncthreads();

    const int warp = tidx >> 5;                   // head
    const int lane = tidx & 31;

    float vals[4];
    #pragma unroll
    for (int m = 0; m < 4; ++m)
        vals[m] = sm[warp * 132 + lane + 32 * m];

    bool used[4] = {false, false, false, false};

    #pragma unroll
    for (int it = 0; it < 4; ++it) {
        float bv = -3.402823466e+38f;
        int   bj = 1 << 30;
        #pragma unroll
        for (int m = 0; m < 4; ++m) {
            int j = lane + 32 * m;
            if (!used[m] && (vals[m] > bv || (vals[m] == bv && j < bj))) {
                bv = vals[m];
                bj = j;
            }
        }
        // Warp argmax, min-index tiebreak.
        #pragma unroll
        for (int m = 16; m; m >>= 1) {
            float ov = __shfl_xor_sync(0xffffffffu, bv, m);
            int   oj = __shfl_xor_sync(0xffffffffu, bj, m);
            if (ov > bv || (ov == bv && oj < bj)) { bv = ov; bj = oj; }
        }
        #pragma unroll
        for (int m = 0; m < 4; ++m)
            if (lane + 32 * m == bj) used[m] = true;

        if (lane == 0) g_colmask[bj] = 1.0f;       // benign race: same value
    }

    // ---- Grid barrier (all 1024 blocks resident) ----
    __syncthreads();
    if (tidx == 0) {
        __threadfence();                            // release colmask writes
        int n = atomicAdd(&g_counter, 1);
        if (n == NROWS - 1) {
            atomicExch(&g_flag, 1);                 // wake everyone
        } else {
            volatile int* f = &g_flag;
            while (*f == 0) { }                     // read-only poll: no LTS
        }                                           // atomic serialization
        __threadfence();                            // acquire
    }
    __syncthreads();

    // ---- Phase B: apply roi * colmask for this row ----
    // float4 chunk tidx covers j = tidx>>1, heads (tidx&1)*4 .. +3.
    const int j = tidx >> 1;
    const float scale = __ldcg(roi + bi * NUM + j) * __ldcg(&g_colmask[j]);

    float4* o4 = reinterpret_cast<float4*>(row);
    float4 x = o4[tidx];
    x.x *= scale; x.y *= scale; x.z *= scale; x.w *= scale;
    o4[tidx] = x;
}

// ---------------------------------------------------------------------------
extern "C" void kernel_launch(void* const* d_in, const int* in_sizes, int n_in,
                              void* d_out, int out_size)
{
    const float* q   = (const float*)d_in[0];
    const float* k   = (const float*)d_in[1];
    const float* roi = (const float*)d_in[2];
    float* out = (float*)d_out;

    attn_kernel<<<NPOS / 4, 256>>>(q, k, out);
    topk_apply_kernel<<<NROWS, 256>>>(out, roi);
}